// round 5
// baseline (speedup 1.0000x reference)
#include <cuda_runtime.h>
#include <cuda_bf16.h>

#define NREF  4096
#define NIN   8192
#define DFEAT 512
#define PDIM  256
#define LDS   40          // 32 + 8 pad (bf16 elems) -> 80B row stride

#define TILE_ELEMS (128 * LDS)
#define TILE_BYTES (TILE_ELEMS * 2)       // 10240
#define STAGE_BYTES (4 * TILE_BYTES)      // 40960: Ah, Al, Bh, Bl
#define SMEM_TOTAL (2 * STAGE_BYTES + 512)

// ---------------- scratch (device globals: allocation-guard safe) ----------
__device__ __nv_bfloat16 g_Xh[NREF * DFEAT];
__device__ __nv_bfloat16 g_Xl[NREF * DFEAT];
__device__ __nv_bfloat16 g_Dh[NIN * DFEAT];
__device__ __nv_bfloat16 g_Dl[NIN * DFEAT];
__device__ __nv_bfloat16 g_Ah[PDIM * NREF];
__device__ __nv_bfloat16 g_Al[PDIM * NREF];
__device__ __nv_bfloat16 g_Kth[(size_t)NIN * NREF];   // K^T hi  [NIN, NREF]
__device__ __nv_bfloat16 g_Ktl[(size_t)NIN * NREF];   // K^T lo

__device__ __forceinline__ unsigned sm32(const void* p) {
    unsigned r;
    asm("{.reg .u64 t; cvta.to.shared.u64 t, %1; cvt.u32.u64 %0, t;}" : "=r"(r) : "l"(p));
    return r;
}

// Load one 128x32 bf16 tile with 128 threads: one row (64B) per thread.
__device__ __forceinline__ void load_tile(unsigned sbuf, const __nv_bfloat16* src,
                                          int rowBase, int K, int kOff, int tid) {
    const char* g = (const char*)(src + (size_t)(rowBase + tid) * K + kOff);
    const unsigned s = sbuf + tid * (LDS * 2);
    asm volatile("cp.async.cg.shared.global [%0], [%1], 16;\n\t"
                 "cp.async.cg.shared.global [%2], [%3], 16;\n\t"
                 "cp.async.cg.shared.global [%4], [%5], 16;\n\t"
                 "cp.async.cg.shared.global [%6], [%7], 16;"
                 :: "r"(s), "l"(g), "r"(s + 16), "l"(g + 16),
                    "r"(s + 32), "l"(g + 32), "r"(s + 48), "l"(g + 48));
}

__device__ __forceinline__ void mma16(float* c, const unsigned* a, unsigned b0, unsigned b1) {
    asm volatile(
        "mma.sync.aligned.m16n8k16.row.col.f32.bf16.bf16.f32 "
        "{%0,%1,%2,%3}, {%4,%5,%6,%7}, {%8,%9}, {%0,%1,%2,%3};"
        : "+f"(c[0]), "+f"(c[1]), "+f"(c[2]), "+f"(c[3])
        : "r"(a[0]), "r"(a[1]), "r"(a[2]), "r"(a[3]), "r"(b0), "r"(b1));
}

#define LDSM4(r, addr)                                                           \
    asm volatile("ldmatrix.sync.aligned.m8n8.x4.shared.b16 {%0,%1,%2,%3}, [%4];" \
                 : "=r"((r)[0]), "=r"((r)[1]), "=r"((r)[2]), "=r"((r)[3])        \
                 : "r"(addr))

// One BLK_K=32 stage, 64x64 warp tile, fused 3-term split accumulation:
//   c += Ah.Bh + Ah.Bl + Al.Bh
__device__ __forceinline__ void compute3_k32(unsigned sAh, unsigned sAl,
                                             unsigned sBh, unsigned sBl,
                                             int warpM, int warpN, int lane,
                                             float (*c)[8][4]) {
#pragma unroll
    for (int kk = 0; kk < 32; kk += 16) {
        unsigned ah[4][4], al[4][4];
#pragma unroll
        for (int mi = 0; mi < 4; mi++) {
            const unsigned aoff =
                ((warpM * 64 + mi * 16 + (lane & 15)) * LDS + kk + (lane >> 4) * 8) * 2;
            LDSM4(ah[mi], sAh + aoff);
            LDSM4(al[mi], sAl + aoff);
        }
#pragma unroll
        for (int g = 0; g < 4; g++) {
            const unsigned boff =
                ((warpN * 64 + g * 16 + (lane & 7) + ((lane >> 4) & 1) * 8) * LDS
                 + kk + ((lane >> 3) & 1) * 8) * 2;
            unsigned bh[4], bl[4];
            LDSM4(bh, sBh + boff);
            LDSM4(bl, sBl + boff);
#pragma unroll
            for (int mi = 0; mi < 4; mi++) {
                mma16(c[mi][2 * g],     ah[mi], bh[0], bh[1]);
                mma16(c[mi][2 * g + 1], ah[mi], bh[2], bh[3]);
                mma16(c[mi][2 * g],     ah[mi], bl[0], bl[1]);
                mma16(c[mi][2 * g + 1], ah[mi], bl[2], bl[3]);
                mma16(c[mi][2 * g],     al[mi], bh[0], bh[1]);
                mma16(c[mi][2 * g + 1], al[mi], bh[2], bh[3]);
            }
        }
    }
}

// ---------------------------------------------------------------------------
// GEMM1 (transposed): Kt[j,i] = mask(Z[j]==Z_ref[i]) * (desc[j].X_ref[i])^expK
// 128 threads / CTA, 4 warps, warp grid 2x2 of 64x64 tiles.
// ---------------------------------------------------------------------------
__global__ __launch_bounds__(128) void gemm1_mma(const int* __restrict__ Zq,
                                                 const int* __restrict__ Zx,
                                                 const int* __restrict__ expKp) {
    extern __shared__ char dynsm[];
    const int tid = threadIdx.x, lane = tid & 31, wid = tid >> 5;
    const int warpM = wid & 1, warpN = wid >> 1;
    const int jBase = blockIdx.y * 128, iBase = blockIdx.x * 128;

    int* Zcol = (int*)(dynsm + 2 * STAGE_BYTES);
    Zcol[tid] = Zx[iBase + tid];

    float c[4][8][4];
#pragma unroll
    for (int i = 0; i < 4; i++)
#pragma unroll
        for (int j = 0; j < 8; j++)
#pragma unroll
            for (int k = 0; k < 4; k++) c[i][j][k] = 0.0f;

    unsigned st[2][4];
#pragma unroll
    for (int s = 0; s < 2; s++)
#pragma unroll
        for (int t = 0; t < 4; t++)
            st[s][t] = sm32(dynsm + s * STAGE_BYTES + t * TILE_BYTES);

    load_tile(st[0][0], g_Dh, jBase, DFEAT, 0, tid);
    load_tile(st[0][1], g_Dl, jBase, DFEAT, 0, tid);
    load_tile(st[0][2], g_Xh, iBase, DFEAT, 0, tid);
    load_tile(st[0][3], g_Xl, iBase, DFEAT, 0, tid);
    asm volatile("cp.async.commit_group;" ::: "memory");

    const int NITER = DFEAT / 32;       // 16
    for (int it = 0; it < NITER; it++) {
        const int b = it & 1;
        if (it + 1 < NITER) {
            const int kOff = (it + 1) * 32;
            load_tile(st[1 - b][0], g_Dh, jBase, DFEAT, kOff, tid);
            load_tile(st[1 - b][1], g_Dl, jBase, DFEAT, kOff, tid);
            load_tile(st[1 - b][2], g_Xh, iBase, DFEAT, kOff, tid);
            load_tile(st[1 - b][3], g_Xl, iBase, DFEAT, kOff, tid);
            asm volatile("cp.async.commit_group;" ::: "memory");
            asm volatile("cp.async.wait_group 1;" ::: "memory");
        } else {
            asm volatile("cp.async.wait_group 0;" ::: "memory");
        }
        __syncthreads();
        compute3_k32(st[b][0], st[b][1], st[b][2], st[b][3], warpM, warpN, lane, c);
        __syncthreads();
    }

    // epilogue: pow, mask, bf16 hi/lo split, store K^T
    const int e = expKp[0];
#pragma unroll
    for (int mi = 0; mi < 4; mi++) {
        const int r0 = jBase + warpM * 64 + mi * 16 + (lane >> 2);
        const int zr0 = Zq[r0], zr1 = Zq[r0 + 8];
        const size_t ro0 = (size_t)r0 * NREF, ro1 = (size_t)(r0 + 8) * NREF;
#pragma unroll
        for (int ni = 0; ni < 8; ni++) {
            const int colL = warpN * 64 + ni * 8 + 2 * (lane & 3);
            const int zc0 = Zcol[colL], zc1 = Zcol[colL + 1];
            float v0 = c[mi][ni][0], v1 = c[mi][ni][1];
            float v2 = c[mi][ni][2], v3 = c[mi][ni][3];
            float p0 = 1.f, p1 = 1.f, p2 = 1.f, p3 = 1.f;
            for (int t = 0; t < e; t++) { p0 *= v0; p1 *= v1; p2 *= v2; p3 *= v3; }
            if (zr0 != zc0) p0 = 0.f;
            if (zr0 != zc1) p1 = 0.f;
            if (zr1 != zc0) p2 = 0.f;
            if (zr1 != zc1) p3 = 0.f;

            __nv_bfloat16 h0 = __float2bfloat16(p0), h1 = __float2bfloat16(p1);
            __nv_bfloat16 h2 = __float2bfloat16(p2), h3 = __float2bfloat16(p3);
            __nv_bfloat162 hh01, hh23, ll01, ll23;
            hh01.x = h0; hh01.y = h1;
            hh23.x = h2; hh23.y = h3;
            ll01.x = __float2bfloat16(p0 - __bfloat162float(h0));
            ll01.y = __float2bfloat16(p1 - __bfloat162float(h1));
            ll23.x = __float2bfloat16(p2 - __bfloat162float(h2));
            ll23.y = __float2bfloat16(p3 - __bfloat162float(h3));

            const size_t cg = (size_t)iBase + colL;
            *(__nv_bfloat162*)(g_Kth + ro0 + cg) = hh01;
            *(__nv_bfloat162*)(g_Kth + ro1 + cg) = hh23;
            *(__nv_bfloat162*)(g_Ktl + ro0 + cg) = ll01;
            *(__nv_bfloat162*)(g_Ktl + ro1 + cg) = ll23;
        }
    }
}

// ---------------------------------------------------------------------------
// GEMM2: Y[p,j] = Alpha[p] . Kt[j]  (Ah.Kh + Ah.Kl + Al.Kh fused per chunk)
// ---------------------------------------------------------------------------
__global__ __launch_bounds__(128) void gemm2_mma(float* __restrict__ Y) {
    extern __shared__ char dynsm[];
    const int tid = threadIdx.x, lane = tid & 31, wid = tid >> 5;
    const int warpM = wid & 1, warpN = wid >> 1;
    const int pBase = blockIdx.y * 128, jBase = blockIdx.x * 128;

    float c[4][8][4];
#pragma unroll
    for (int i = 0; i < 4; i++)
#pragma unroll
        for (int j = 0; j < 8; j++)
#pragma unroll
            for (int k = 0; k < 4; k++) c[i][j][k] = 0.0f;

    unsigned st[2][4];
#pragma unroll
    for (int s = 0; s < 2; s++)
#pragma unroll
        for (int t = 0; t < 4; t++)
            st[s][t] = sm32(dynsm + s * STAGE_BYTES + t * TILE_BYTES);

    load_tile(st[0][0], g_Ah, pBase, NREF, 0, tid);
    load_tile(st[0][1], g_Al, pBase, NREF, 0, tid);
    load_tile(st[0][2], g_Kth, jBase, NREF, 0, tid);
    load_tile(st[0][3], g_Ktl, jBase, NREF, 0, tid);
    asm volatile("cp.async.commit_group;" ::: "memory");

    const int NITER = NREF / 32;        // 128
    for (int it = 0; it < NITER; it++) {
        const int b = it & 1;
        if (it + 1 < NITER) {
            const int kOff = (it + 1) * 32;
            load_tile(st[1 - b][0], g_Ah, pBase, NREF, kOff, tid);
            load_tile(st[1 - b][1], g_Al, pBase, NREF, kOff, tid);
            load_tile(st[1 - b][2], g_Kth, jBase, NREF, kOff, tid);
            load_tile(st[1 - b][3], g_Ktl, jBase, NREF, kOff, tid);
            asm volatile("cp.async.commit_group;" ::: "memory");
            asm volatile("cp.async.wait_group 1;" ::: "memory");
        } else {
            asm volatile("cp.async.wait_group 0;" ::: "memory");
        }
        __syncthreads();
        compute3_k32(st[b][0], st[b][1], st[b][2], st[b][3], warpM, warpN, lane, c);
        __syncthreads();
    }

#pragma unroll
    for (int mi = 0; mi < 4; mi++) {
        const int r0 = pBase + warpM * 64 + mi * 16 + (lane >> 2);
        const size_t ro0 = (size_t)r0 * NIN, ro1 = (size_t)(r0 + 8) * NIN;
#pragma unroll
        for (int ni = 0; ni < 8; ni++) {
            const int col = jBase + warpN * 64 + ni * 8 + 2 * (lane & 3);
            *(float2*)(Y + ro0 + col) = make_float2(c[mi][ni][0], c[mi][ni][1]);
            *(float2*)(Y + ro1 + col) = make_float2(c[mi][ni][2], c[mi][ni][3]);
        }
    }
}

// ---------------------------------------------------------------------------
// fp32 -> bf16 hi/lo splits
// ---------------------------------------------------------------------------
__device__ __forceinline__ void split2(float2 v, __nv_bfloat162* hp, __nv_bfloat162* lp, int i) {
    __nv_bfloat16 h0 = __float2bfloat16(v.x), h1 = __float2bfloat16(v.y);
    __nv_bfloat162 hh, ll;
    hh.x = h0; hh.y = h1;
    ll.x = __float2bfloat16(v.x - __bfloat162float(h0));
    ll.y = __float2bfloat16(v.y - __bfloat162float(h1));
    hp[i] = hh; lp[i] = ll;
}
__global__ void split_X(const float* __restrict__ x) {
    int i = blockIdx.x * blockDim.x + threadIdx.x;
    if (i < NREF * DFEAT / 2)
        split2(((const float2*)x)[i], (__nv_bfloat162*)g_Xh, (__nv_bfloat162*)g_Xl, i);
}
__global__ void split_D(const float* __restrict__ x) {
    int i = blockIdx.x * blockDim.x + threadIdx.x;
    if (i < NIN * DFEAT / 2)
        split2(((const float2*)x)[i], (__nv_bfloat162*)g_Dh, (__nv_bfloat162*)g_Dl, i);
}
__global__ void split_A(const float* __restrict__ x) {
    int i = blockIdx.x * blockDim.x + threadIdx.x;
    if (i < PDIM * NREF / 2)
        split2(((const float2*)x)[i], (__nv_bfloat162*)g_Ah, (__nv_bfloat162*)g_Al, i);
}

extern "C" void kernel_launch(void* const* d_in, const int* in_sizes, int n_in,
                              void* d_out, int out_size) {
    const float* Alpha = (const float*)d_in[0];
    const float* X_ref = (const float*)d_in[1];
    const float* desc  = (const float*)d_in[2];
    const int*   Z_ref = (const int*)d_in[3];
    const int*   Z     = (const int*)d_in[4];
    const int*   expK  = (const int*)d_in[5];
    float* Y = (float*)d_out;

    cudaFuncSetAttribute(gemm1_mma, cudaFuncAttributeMaxDynamicSharedMemorySize, SMEM_TOTAL);
    cudaFuncSetAttribute(gemm2_mma, cudaFuncAttributeMaxDynamicSharedMemorySize, SMEM_TOTAL);

    split_X<<<(NREF * DFEAT / 2 + 255) / 256, 256>>>(X_ref);
    split_D<<<(NIN * DFEAT / 2 + 255) / 256, 256>>>(desc);
    split_A<<<(PDIM * NREF / 2 + 255) / 256, 256>>>(Alpha);

    gemm1_mma<<<dim3(NREF / 128, NIN / 128), 128, SMEM_TOTAL>>>(Z, Z_ref, expK);
    gemm2_mma<<<dim3(NIN / 128, PDIM / 128), 128, SMEM_TOTAL>>>(Y);
}

// round 6
// speedup vs baseline: 1.2926x; 1.2926x over previous
#include <cuda_runtime.h>
#include <cuda_bf16.h>

#define NREF  4096
#define NIN   8192
#define DFEAT 512
#define PDIM  256
#define LDS   40          // 32 + 8 pad (bf16 elems) -> 80B row stride

#define TILE_ELEMS (128 * LDS)
#define TILE_BYTES (TILE_ELEMS * 2)       // 10240
#define STAGE_BYTES (4 * TILE_BYTES)      // 40960: Ah, Al, Bh, Bl
#define SMEM_TOTAL (2 * STAGE_BYTES + 512)

// ---------------- scratch (device globals: allocation-guard safe) ----------
__device__ __nv_bfloat16 g_Xh[NREF * DFEAT];
__device__ __nv_bfloat16 g_Xl[NREF * DFEAT];
__device__ __nv_bfloat16 g_Dh[NIN * DFEAT];
__device__ __nv_bfloat16 g_Dl[NIN * DFEAT];
__device__ __nv_bfloat16 g_Ah[PDIM * NREF];
__device__ __nv_bfloat16 g_Al[PDIM * NREF];
__device__ __nv_bfloat16 g_Kth[(size_t)NIN * NREF];   // K^T hi  [NIN, NREF]
__device__ __nv_bfloat16 g_Ktl[(size_t)NIN * NREF];   // K^T lo

__device__ __forceinline__ unsigned sm32(const void* p) {
    unsigned r;
    asm("{.reg .u64 t; cvta.to.shared.u64 t, %1; cvt.u32.u64 %0, t;}" : "=r"(r) : "l"(p));
    return r;
}

// Load one 128x32 bf16 tile (row-major source, row stride K elems) via cp.async.
__device__ __forceinline__ void load_tile(unsigned sbuf, const __nv_bfloat16* src,
                                          int rowBase, int K, int kOff, int tid) {
    const int row = tid >> 1;
    const char* g = (const char*)(src + (size_t)(rowBase + row) * K + kOff + (tid & 1) * 16);
    const unsigned s = sbuf + row * (LDS * 2) + (tid & 1) * 32;
    asm volatile("cp.async.cg.shared.global [%0], [%1], 16;\n\t"
                 "cp.async.cg.shared.global [%2], [%3], 16;"
                 :: "r"(s), "l"(g), "r"(s + 16), "l"(g + 16));
}

__device__ __forceinline__ void mma16(float* c, const unsigned* a, unsigned b0, unsigned b1) {
    asm volatile(
        "mma.sync.aligned.m16n8k16.row.col.f32.bf16.bf16.f32 "
        "{%0,%1,%2,%3}, {%4,%5,%6,%7}, {%8,%9}, {%0,%1,%2,%3};"
        : "+f"(c[0]), "+f"(c[1]), "+f"(c[2]), "+f"(c[3])
        : "r"(a[0]), "r"(a[1]), "r"(a[2]), "r"(a[3]), "r"(b0), "r"(b1));
}

#define LDSM4(r, addr)                                                           \
    asm volatile("ldmatrix.sync.aligned.m8n8.x4.shared.b16 {%0,%1,%2,%3}, [%4];" \
                 : "=r"((r)[0]), "=r"((r)[1]), "=r"((r)[2]), "=r"((r)[3])        \
                 : "r"(addr))

// One BLK_K=32 stage (32x64 warp tile), fused 3-term split accumulation:
//   c += Ah.Bh + Ah.Bl + Al.Bh
// Terms ordered outermost per g-group so same-accumulator MMAs sit at
// distance 4 (breaks the HMMA dependency chain that capped issue rate).
__device__ __forceinline__ void compute3_k32(unsigned sAh, unsigned sAl,
                                             unsigned sBh, unsigned sBl,
                                             int warpM, int warpN, int lane,
                                             float (*c)[8][4]) {
#pragma unroll
    for (int kk = 0; kk < 32; kk += 16) {
        const unsigned aoff = ((warpM * 32 + (lane & 15)) * LDS + kk + (lane >> 4) * 8) * 2;
        unsigned ah[2][4], al[2][4];
        LDSM4(ah[0], sAh + aoff);
        LDSM4(ah[1], sAh + aoff + 16 * LDS * 2);
        LDSM4(al[0], sAl + aoff);
        LDSM4(al[1], sAl + aoff + 16 * LDS * 2);
#pragma unroll
        for (int g = 0; g < 4; g++) {
            const unsigned boff = ((warpN * 64 + g * 16 + (lane & 7) + ((lane >> 4) & 1) * 8) * LDS
                                   + kk + ((lane >> 3) & 1) * 8) * 2;
            unsigned bh[4], bl[4];
            LDSM4(bh, sBh + boff);
            LDSM4(bl, sBl + boff);
            // term Ah.Bh  (4 MMAs, 4 distinct accumulators)
            mma16(c[0][2 * g],     ah[0], bh[0], bh[1]);
            mma16(c[0][2 * g + 1], ah[0], bh[2], bh[3]);
            mma16(c[1][2 * g],     ah[1], bh[0], bh[1]);
            mma16(c[1][2 * g + 1], ah[1], bh[2], bh[3]);
            // term Ah.Bl
            mma16(c[0][2 * g],     ah[0], bl[0], bl[1]);
            mma16(c[0][2 * g + 1], ah[0], bl[2], bl[3]);
            mma16(c[1][2 * g],     ah[1], bl[0], bl[1]);
            mma16(c[1][2 * g + 1], ah[1], bl[2], bl[3]);
            // term Al.Bh
            mma16(c[0][2 * g],     al[0], bh[0], bh[1]);
            mma16(c[0][2 * g + 1], al[0], bh[2], bh[3]);
            mma16(c[1][2 * g],     al[1], bh[0], bh[1]);
            mma16(c[1][2 * g + 1], al[1], bh[2], bh[3]);
        }
    }
}

// ---------------------------------------------------------------------------
// GEMM1 (transposed): Kt[j,i] = mask(Z[j]==Z_ref[i]) * (desc[j].X_ref[i])^expK
// 256 threads / CTA, 8 warps, warp grid 4x2 of 32x64 tiles.
// ---------------------------------------------------------------------------
__global__ __launch_bounds__(256, 2) void gemm1_mma(const int* __restrict__ Zq,
                                                    const int* __restrict__ Zx,
                                                    const int* __restrict__ expKp) {
    extern __shared__ char dynsm[];
    const int tid = threadIdx.x, lane = tid & 31, wid = tid >> 5;
    const int warpM = wid & 3, warpN = wid >> 2;
    const int jBase = blockIdx.y * 128, iBase = blockIdx.x * 128;

    int* Zcol = (int*)(dynsm + 2 * STAGE_BYTES);
    if (tid < 128) Zcol[tid] = Zx[iBase + tid];

    float c[2][8][4];
#pragma unroll
    for (int i = 0; i < 2; i++)
#pragma unroll
        for (int j = 0; j < 8; j++)
#pragma unroll
            for (int k = 0; k < 4; k++) c[i][j][k] = 0.0f;

    unsigned st[2][4];
#pragma unroll
    for (int s = 0; s < 2; s++)
#pragma unroll
        for (int t = 0; t < 4; t++)
            st[s][t] = sm32(dynsm + s * STAGE_BYTES + t * TILE_BYTES);

    load_tile(st[0][0], g_Dh, jBase, DFEAT, 0, tid);
    load_tile(st[0][1], g_Dl, jBase, DFEAT, 0, tid);
    load_tile(st[0][2], g_Xh, iBase, DFEAT, 0, tid);
    load_tile(st[0][3], g_Xl, iBase, DFEAT, 0, tid);
    asm volatile("cp.async.commit_group;" ::: "memory");

    const int NITER = DFEAT / 32;       // 16
    for (int it = 0; it < NITER; it++) {
        const int b = it & 1;
        if (it + 1 < NITER) {
            const int kOff = (it + 1) * 32;
            load_tile(st[1 - b][0], g_Dh, jBase, DFEAT, kOff, tid);
            load_tile(st[1 - b][1], g_Dl, jBase, DFEAT, kOff, tid);
            load_tile(st[1 - b][2], g_Xh, iBase, DFEAT, kOff, tid);
            load_tile(st[1 - b][3], g_Xl, iBase, DFEAT, kOff, tid);
            asm volatile("cp.async.commit_group;" ::: "memory");
            asm volatile("cp.async.wait_group 1;" ::: "memory");
        } else {
            asm volatile("cp.async.wait_group 0;" ::: "memory");
        }
        __syncthreads();
        compute3_k32(st[b][0], st[b][1], st[b][2], st[b][3], warpM, warpN, lane, c);
        __syncthreads();
    }

    // epilogue: pow, mask, bf16 hi/lo split, store K^T
    const int e = expKp[0];
#pragma unroll
    for (int mi = 0; mi < 2; mi++) {
        const int r0 = jBase + warpM * 32 + mi * 16 + (lane >> 2);
        const int zr0 = Zq[r0], zr1 = Zq[r0 + 8];
        const size_t ro0 = (size_t)r0 * NREF, ro1 = (size_t)(r0 + 8) * NREF;
#pragma unroll
        for (int ni = 0; ni < 8; ni++) {
            const int colL = warpN * 64 + ni * 8 + 2 * (lane & 3);
            const int zc0 = Zcol[colL], zc1 = Zcol[colL + 1];
            float v0 = c[mi][ni][0], v1 = c[mi][ni][1];
            float v2 = c[mi][ni][2], v3 = c[mi][ni][3];
            float p0 = 1.f, p1 = 1.f, p2 = 1.f, p3 = 1.f;
            for (int t = 0; t < e; t++) { p0 *= v0; p1 *= v1; p2 *= v2; p3 *= v3; }
            if (zr0 != zc0) p0 = 0.f;
            if (zr0 != zc1) p1 = 0.f;
            if (zr1 != zc0) p2 = 0.f;
            if (zr1 != zc1) p3 = 0.f;

            __nv_bfloat16 h0 = __float2bfloat16(p0), h1 = __float2bfloat16(p1);
            __nv_bfloat16 h2 = __float2bfloat16(p2), h3 = __float2bfloat16(p3);
            __nv_bfloat162 hh01, hh23, ll01, ll23;
            hh01.x = h0; hh01.y = h1;
            hh23.x = h2; hh23.y = h3;
            ll01.x = __float2bfloat16(p0 - __bfloat162float(h0));
            ll01.y = __float2bfloat16(p1 - __bfloat162float(h1));
            ll23.x = __float2bfloat16(p2 - __bfloat162float(h2));
            ll23.y = __float2bfloat16(p3 - __bfloat162float(h3));

            const size_t cg = (size_t)iBase + colL;
            *(__nv_bfloat162*)(g_Kth + ro0 + cg) = hh01;
            *(__nv_bfloat162*)(g_Kth + ro1 + cg) = hh23;
            *(__nv_bfloat162*)(g_Ktl + ro0 + cg) = ll01;
            *(__nv_bfloat162*)(g_Ktl + ro1 + cg) = ll23;
        }
    }
}

// ---------------------------------------------------------------------------
// GEMM2: Y[p,j] = Alpha[p] . Kt[j]  (Ah.Kh + Ah.Kl + Al.Kh fused per chunk)
// ---------------------------------------------------------------------------
__global__ __launch_bounds__(256, 2) void gemm2_mma(float* __restrict__ Y) {
    extern __shared__ char dynsm[];
    const int tid = threadIdx.x, lane = tid & 31, wid = tid >> 5;
    const int warpM = wid & 3, warpN = wid >> 2;
    const int pBase = blockIdx.y * 128, jBase = blockIdx.x * 128;

    float c[2][8][4];
#pragma unroll
    for (int i = 0; i < 2; i++)
#pragma unroll
        for (int j = 0; j < 8; j++)
#pragma unroll
            for (int k = 0; k < 4; k++) c[i][j][k] = 0.0f;

    unsigned st[2][4];
#pragma unroll
    for (int s = 0; s < 2; s++)
#pragma unroll
        for (int t = 0; t < 4; t++)
            st[s][t] = sm32(dynsm + s * STAGE_BYTES + t * TILE_BYTES);

    load_tile(st[0][0], g_Ah, pBase, NREF, 0, tid);
    load_tile(st[0][1], g_Al, pBase, NREF, 0, tid);
    load_tile(st[0][2], g_Kth, jBase, NREF, 0, tid);
    load_tile(st[0][3], g_Ktl, jBase, NREF, 0, tid);
    asm volatile("cp.async.commit_group;" ::: "memory");

    const int NITER = NREF / 32;        // 128
    for (int it = 0; it < NITER; it++) {
        const int b = it & 1;
        if (it + 1 < NITER) {
            const int kOff = (it + 1) * 32;
            load_tile(st[1 - b][0], g_Ah, pBase, NREF, kOff, tid);
            load_tile(st[1 - b][1], g_Al, pBase, NREF, kOff, tid);
            load_tile(st[1 - b][2], g_Kth, jBase, NREF, kOff, tid);
            load_tile(st[1 - b][3], g_Ktl, jBase, NREF, kOff, tid);
            asm volatile("cp.async.commit_group;" ::: "memory");
            asm volatile("cp.async.wait_group 1;" ::: "memory");
        } else {
            asm volatile("cp.async.wait_group 0;" ::: "memory");
        }
        __syncthreads();
        compute3_k32(st[b][0], st[b][1], st[b][2], st[b][3], warpM, warpN, lane, c);
        __syncthreads();
    }

#pragma unroll
    for (int mi = 0; mi < 2; mi++) {
        const int r0 = pBase + warpM * 32 + mi * 16 + (lane >> 2);
        const size_t ro0 = (size_t)r0 * NIN, ro1 = (size_t)(r0 + 8) * NIN;
#pragma unroll
        for (int ni = 0; ni < 8; ni++) {
            const int col = jBase + warpN * 64 + ni * 8 + 2 * (lane & 3);
            *(float2*)(Y + ro0 + col) = make_float2(c[mi][ni][0], c[mi][ni][1]);
            *(float2*)(Y + ro1 + col) = make_float2(c[mi][ni][2], c[mi][ni][3]);
        }
    }
}

// ---------------------------------------------------------------------------
// fp32 -> bf16 hi/lo splits
// ---------------------------------------------------------------------------
__device__ __forceinline__ void split2(float2 v, __nv_bfloat162* hp, __nv_bfloat162* lp, int i) {
    __nv_bfloat16 h0 = __float2bfloat16(v.x), h1 = __float2bfloat16(v.y);
    __nv_bfloat162 hh, ll;
    hh.x = h0; hh.y = h1;
    ll.x = __float2bfloat16(v.x - __bfloat162float(h0));
    ll.y = __float2bfloat16(v.y - __bfloat162float(h1));
    hp[i] = hh; lp[i] = ll;
}
__global__ void split_X(const float* __restrict__ x) {
    int i = blockIdx.x * blockDim.x + threadIdx.x;
    if (i < NREF * DFEAT / 2)
        split2(((const float2*)x)[i], (__nv_bfloat162*)g_Xh, (__nv_bfloat162*)g_Xl, i);
}
__global__ void split_D(const float* __restrict__ x) {
    int i = blockIdx.x * blockDim.x + threadIdx.x;
    if (i < NIN * DFEAT / 2)
        split2(((const float2*)x)[i], (__nv_bfloat162*)g_Dh, (__nv_bfloat162*)g_Dl, i);
}
__global__ void split_A(const float* __restrict__ x) {
    int i = blockIdx.x * blockDim.x + threadIdx.x;
    if (i < PDIM * NREF / 2)
        split2(((const float2*)x)[i], (__nv_bfloat162*)g_Ah, (__nv_bfloat162*)g_Al, i);
}

extern "C" void kernel_launch(void* const* d_in, const int* in_sizes, int n_in,
                              void* d_out, int out_size) {
    const float* Alpha = (const float*)d_in[0];
    const float* X_ref = (const float*)d_in[1];
    const float* desc  = (const float*)d_in[2];
    const int*   Z_ref = (const int*)d_in[3];
    const int*   Z     = (const int*)d_in[4];
    const int*   expK  = (const int*)d_in[5];
    float* Y = (float*)d_out;

    cudaFuncSetAttribute(gemm1_mma, cudaFuncAttributeMaxDynamicSharedMemorySize, SMEM_TOTAL);
    cudaFuncSetAttribute(gemm2_mma, cudaFuncAttributeMaxDynamicSharedMemorySize, SMEM_TOTAL);

    split_X<<<(NREF * DFEAT / 2 + 255) / 256, 256>>>(X_ref);
    split_D<<<(NIN * DFEAT / 2 + 255) / 256, 256>>>(desc);
    split_A<<<(PDIM * NREF / 2 + 255) / 256, 256>>>(Alpha);

    gemm1_mma<<<dim3(NREF / 128, NIN / 128), 256, SMEM_TOTAL>>>(Z, Z_ref, expK);
    gemm2_mma<<<dim3(NIN / 128, PDIM / 128), 256, SMEM_TOTAL>>>(Y);
}